// round 14
// baseline (speedup 1.0000x reference)
#include <cuda_runtime.h>
#include <cstdint>

#define dH 16
#define dD 1024
#define dE 64
#define dN 4096
#define dK 256
#define QKV_LD 3072
#define NSPLIT 8

// ---------------- scratch (static device globals: allocation-free) ----------
__device__ float g_qkv[(size_t)dN * QKV_LD];            // (N, 3*H*E): q|k|v (tf32-rounded)
__device__ float g_part[(size_t)NSPLIT * 32 * dK * dE]; // split-K partials for kp/vp
__device__ float g_kp[(size_t)dH * dK * dE];            // (H, K, E) rounded
__device__ float g_vp[(size_t)dH * dK * dE];            // (H, K, E) rounded
__device__ float g_kp2[(size_t)dH * dK * dE];           // kp B-fragment-vector layout
__device__ float g_vp2[(size_t)dH * dK * dE];           // vp pi-permuted B-frag layout
__device__ float g_z[(size_t)dN * (dH * dE)];           // (N, H*E) rounded
__device__ float g_x32[(size_t)dN * dD];                // X rounded + fragment-permuted
__device__ float g_w32[(size_t)3 * 1024 * dD];          // [Wq;Wk;Wv] rounded + permuted
__device__ float g_b32[3072];                           // [bq|bk|bv] (fp32)
__device__ float g_wo32[(size_t)dE * 1024];             // Wo rounded (64 x 1024 row-major)

// ---------------- helpers ---------------------------------------------------
static __device__ __forceinline__ uint32_t f2tf(float x) {
    uint32_t u;
    asm("cvt.rna.tf32.f32 %0, %1;" : "=r"(u) : "f"(x));
    return u;
}
static __device__ __forceinline__ float rndf(float x) { return __uint_as_float(f2tf(x)); }
static __device__ __forceinline__ float4 rnd4(float4 v) {
    v.x = rndf(v.x); v.y = rndf(v.y); v.z = rndf(v.z); v.w = rndf(v.w);
    return v;
}

static __device__ __forceinline__ void mma_m16n8k8(float c[4],
        uint32_t a0, uint32_t a1, uint32_t a2, uint32_t a3,
        uint32_t b0, uint32_t b1) {
    asm volatile(
        "mma.sync.aligned.m16n8k8.row.col.f32.tf32.tf32.f32 "
        "{%0,%1,%2,%3}, {%4,%5,%6,%7}, {%8,%9}, {%0,%1,%2,%3};\n"
        : "+f"(c[0]), "+f"(c[1]), "+f"(c[2]), "+f"(c[3])
        : "r"(a0), "r"(a1), "r"(a2), "r"(a3), "r"(b0), "r"(b1));
}

static __device__ __forceinline__ void cpa(float* s, const float* g) {
    uint32_t sa = (uint32_t)__cvta_generic_to_shared(s);
    asm volatile("cp.async.cg.shared.global [%0], [%1], 16;\n" :: "r"(sa), "l"(g));
}
static __device__ __forceinline__ void cpa_u(uint32_t sa, const float* g) {
    asm volatile("cp.async.cg.shared.global [%0], [%1], 16;\n" :: "r"(sa), "l"(g));
}
#define CP_COMMIT() asm volatile("cp.async.commit_group;\n")
#define CP_WAIT(n)  asm volatile("cp.async.wait_group %0;\n" :: "n"(n))

// ======================= Kernel Pre: round + permute (round-5 proven) =======
__global__ void __launch_bounds__(256, 1)
kPre(const float* __restrict__ X,
     const float* __restrict__ Wq, const float* __restrict__ Wk, const float* __restrict__ Wv,
     const float* __restrict__ bq, const float* __restrict__ bk, const float* __restrict__ bv,
     const float* __restrict__ Wo)
{
    int i = blockIdx.x * 256 + threadIdx.x;
    if (i < 1048576) {               // ---- X permute (1M float4)
        int blk = i >> 10, w = i & 1023;
        int mb = blk >> 5, kb = blk & 31;
        int t = w & 3, g = (w >> 2) & 7, ks = (w >> 5) & 3, mt = (w >> 7) & 3, wr = (w >> 9) & 1;
        int row = mb * 128 + wr * 64 + mt * 16 + g;
        int col = kb * 32 + ks * 8 + t;
        const float* xr0 = X + (size_t)row * dD;
        const float* xr1 = xr0 + 8 * dD;
        float4 v = { xr0[col], xr1[col], xr0[col + 4], xr1[col + 4] };
        ((float4*)g_x32)[i] = rnd4(v);
        return;
    }
    int j = i - 1048576;
    if (j < 786432) {                // ---- W permute (768K float4)
        int blk = j >> 10, w = j & 1023;
        int nb = blk >> 5, kb = blk & 31;
        int t = w & 3, g = (w >> 2) & 7, kp = (w >> 5) & 1, nt = (w >> 6) & 3, wc = (w >> 8) & 3;
        int n = nb * 128 + wc * 32 + nt * 8 + g;
        int col = kb * 32 + kp * 16 + t;
        const float* Wsrc = (n < 1024) ? (Wq + (size_t)n * dD)
                          : (n < 2048) ? (Wk + (size_t)(n - 1024) * dD)
                                       : (Wv + (size_t)(n - 2048) * dD);
        float4 v = { Wsrc[col], Wsrc[col + 4], Wsrc[col + 8], Wsrc[col + 12] };
        ((float4*)g_w32)[j] = rnd4(v);
        return;
    }
    int k2 = j - 786432;
    if (k2 < 16384) {                // ---- Wo round: 64*1024 floats = 16384 float4
        ((float4*)g_wo32)[k2] = rnd4(((const float4*)Wo)[k2]);
        return;
    }
    int b = k2 - 16384;              // ---- biases (0..767 float4)
    if (b < 768) {
        const float4* src = (b < 256) ? ((const float4*)bq + b)
                           : (b < 512) ? ((const float4*)bk + (b - 256))
                                       : ((const float4*)bv + (b - 512));
        ((float4*)g_b32)[b] = *src;
    }
}

// ======================= Kernel A: QKV projection (round-9 proven) ==========
#define KA_STG   3
#define KA_STGB  32768
#define KA_SMEM  (KA_STG * KA_STGB)
__global__ void __launch_bounds__(256, 2)
kA()
{
    extern __shared__ char smc[];
    const uint32_t sb = (uint32_t)__cvta_generic_to_shared(smc);
    const int tid = threadIdx.x, wid = tid >> 5, lane = tid & 31;
    const int g = lane >> 2, t = lane & 3;
    const int wr = wid >> 2, wc = wid & 3;     // 2x4 warp grid, warp tile 64x32
    const int nb = blockIdx.x;                 // 24 feature tiles
    const int mb = blockIdx.y;                 // 32 sequence tiles

    auto load_stage = [&](int s, int kt) {
        const float* srcA = g_x32 + (size_t)(mb * 32 + kt) * 4096;
        const float* srcB = g_w32 + (size_t)(nb * 32 + kt) * 4096;
        const uint32_t dA = sb + s * KA_STGB;
        const uint32_t dB = dA + 16384;
#pragma unroll
        for (int i = 0; i < 4; i++) cpa_u(dA + (tid + i * 256) * 16, srcA + (tid + i * 256) * 4);
#pragma unroll
        for (int i = 0; i < 4; i++) cpa_u(dB + (tid + i * 256) * 16, srcB + (tid + i * 256) * 4);
        CP_COMMIT();
    };

    float acc[4][4][4];
#pragma unroll
    for (int a = 0; a < 4; a++)
#pragma unroll
        for (int b = 0; b < 4; b++)
#pragma unroll
            for (int c = 0; c < 4; c++) acc[a][b][c] = 0.f;

    load_stage(0, 0);
    load_stage(1, 1);

    for (int kt = 0; kt < 32; kt++) {
        const int s = kt % KA_STG;
        if (kt + 2 < 32) { load_stage((kt + 2) % KA_STG, kt + 2); CP_WAIT(2); }
        else if (kt == 30) { CP_WAIT(1); }
        else               { CP_WAIT(0); }
        __syncthreads();

        const char* sA = smc + s * KA_STGB + (size_t)(wr * 512 + g * 4 + t) * 16;
        const char* sB = smc + s * KA_STGB + 16384 + (size_t)(wc * 256 + g * 4 + t) * 16;
#pragma unroll
        for (int kp = 0; kp < 2; kp++) {
            uint4 bv[4];
#pragma unroll
            for (int nt = 0; nt < 4; nt++)
                bv[nt] = *(const uint4*)(sB + (size_t)(nt * 64 + kp * 32) * 16);
#pragma unroll
            for (int ki = 0; ki < 2; ki++) {
                const int ks = kp * 2 + ki;
                uint4 av[4];
#pragma unroll
                for (int mt = 0; mt < 4; mt++)
                    av[mt] = *(const uint4*)(sA + (size_t)(mt * 128 + ks * 32) * 16);
#pragma unroll
                for (int nt = 0; nt < 4; nt++) {
                    uint32_t b0 = ki ? bv[nt].z : bv[nt].x;
                    uint32_t b1 = ki ? bv[nt].w : bv[nt].y;
#pragma unroll
                    for (int mt = 0; mt < 4; mt++)
                        mma_m16n8k8(acc[mt][nt], av[mt].x, av[mt].y, av[mt].z, av[mt].w, b0, b1);
                }
            }
        }
        __syncthreads();
    }

    const int r0 = nb * 128, m0 = mb * 128;
#pragma unroll
    for (int mt = 0; mt < 4; mt++) {
#pragma unroll
        for (int nt = 0; nt < 4; nt++) {
            int row = m0 + wr * 64 + mt * 16 + g;
            int col = r0 + wc * 32 + nt * 8 + 2 * t;
            float b0 = g_b32[col], b1 = g_b32[col + 1];
            float2 v0 = { rndf(acc[mt][nt][0] + b0), rndf(acc[mt][nt][1] + b1) };
            float2 v1 = { rndf(acc[mt][nt][2] + b0), rndf(acc[mt][nt][3] + b1) };
            *(float2*)&g_qkv[(size_t)row * QKV_LD + col] = v0;
            *(float2*)&g_qkv[(size_t)(row + 8) * QKV_LD + col] = v1;
        }
    }
}

// ======================= Kernel B: kp/vp (M-tile 128, occ 3) ================
// grid (8 ksplits, 64): blockIdx.y = matrix m (0..31) * 2 + row-half rh.
// Per CTA: 128x64 output over one 512-k chunk. smem 54KB, ~80 regs -> occ 3.
#define B_SMEM_BYTES ((2u * 128u * 36u + 2u * 32u * 72u) * 4u)
__global__ void __launch_bounds__(256, 3)
kB(const float* __restrict__ Ew, const float* __restrict__ Fw)
{
    extern __shared__ float sm[];
    float* As = sm;                   // [2][128][36]
    float* Bs = sm + 2 * 128 * 36;    // [2][32][72]
    const int tid = threadIdx.x;
    const int s = blockIdx.x;         // ksplit 0..7
    const int mm = blockIdx.y;        // 0..63
    const int m = mm >> 1, rh = mm & 1;
    const float* Aw = ((m < 16) ? (Ew + (size_t)m * dK * dN)
                                : (Fw + (size_t)(m - 16) * dK * dN))
                      + (size_t)(rh * 128) * dN;
    const int cbase = (m < 16) ? (1024 + m * 64) : (2048 + (m - 16) * 64);
    const int kbase0 = s * 512;

    auto load_tile = [&](int buf, int kb) {
        float* dA = As + buf * 128 * 36;
        float* dB = Bs + buf * 32 * 72;
#pragma unroll
        for (int i = 0; i < 4; i++) {
            int e = tid + i * 256;
            int row = e >> 3, q = e & 7;
            cpa(dA + row * 36 + q * 4, Aw + (size_t)row * dN + kb + q * 4);
        }
#pragma unroll
        for (int i = 0; i < 2; i++) {
            int e = tid + i * 256;
            int row = e >> 4, q = e & 15;
            cpa(dB + row * 72 + q * 4, g_qkv + (size_t)(kb + row) * QKV_LD + cbase + q * 4);
        }
    };

    const int lane = tid & 31, w = tid >> 5;
    const int g = lane >> 2, t = lane & 3;
    const int wr = w >> 1, wc = w & 1;   // 4x2 warp grid, warp tile 32x32

    float acc[2][4][4];
#pragma unroll
    for (int a = 0; a < 2; a++)
#pragma unroll
        for (int b = 0; b < 4; b++)
#pragma unroll
            for (int c = 0; c < 4; c++) acc[a][b][c] = 0.f;

    load_tile(0, kbase0);
    CP_COMMIT();
    const int NKT = 512 / 32;            // 16
    for (int kt = 0; kt < NKT; kt++) {
        if (kt + 1 < NKT) { load_tile((kt + 1) & 1, kbase0 + (kt + 1) * 32); CP_COMMIT(); CP_WAIT(1); }
        else              { CP_WAIT(0); }
        __syncthreads();
        const float* A = As + (kt & 1) * 128 * 36;
        const float* B = Bs + (kt & 1) * 32 * 72;
#pragma unroll
        for (int ks = 0; ks < 4; ks++) {
            const int k = ks * 8;
            uint32_t af[2][4];
#pragma unroll
            for (int mt = 0; mt < 2; mt++) {
                const float* ap = A + (wr * 32 + mt * 16 + g) * 36 + k + t;
                af[mt][0] = f2tf(ap[0]);
                af[mt][1] = f2tf(ap[8 * 36]);
                af[mt][2] = f2tf(ap[4]);
                af[mt][3] = f2tf(ap[8 * 36 + 4]);
            }
#pragma unroll
            for (int nt = 0; nt < 4; nt++) {
                const int col = wc * 32 + nt * 8 + g;
                uint32_t b0 = __float_as_uint(B[(k + t) * 72 + col]);       // pre-rounded
                uint32_t b1 = __float_as_uint(B[(k + t + 4) * 72 + col]);
#pragma unroll
                for (int mt = 0; mt < 2; mt++)
                    mma_m16n8k8(acc[mt][nt], af[mt][0], af[mt][1], af[mt][2], af[mt][3], b0, b1);
            }
        }
        __syncthreads();
    }

    float* base = g_part + (size_t)(s * 32 + m) * (dK * dE);
#pragma unroll
    for (int mt = 0; mt < 2; mt++) {
#pragma unroll
        for (int nt = 0; nt < 4; nt++) {
            int j = rh * 128 + wr * 32 + mt * 16 + g;
            int e = wc * 32 + nt * 8 + 2 * t;
            float2 v0 = { acc[mt][nt][0], acc[mt][nt][1] };
            float2 v1 = { acc[mt][nt][2], acc[mt][nt][3] };
            *(float2*)&base[(size_t)j * dE + e] = v0;
            *(float2*)&base[(size_t)(j + 8) * dE + e] = v1;
        }
    }
}

// ======================= Kernel B2: split-K reduce + bias + round ===========
__global__ void __launch_bounds__(256, 1)
kB2(const float* __restrict__ Eb, const float* __restrict__ Fb)
{
    int idx = blockIdx.x * 256 + threadIdx.x;    // float4 index, 131072 total
    int m = idx >> 12;
    int r = idx & 4095;
    int j = r >> 4;
    float4 sum = make_float4(0.f, 0.f, 0.f, 0.f);
#pragma unroll
    for (int s = 0; s < NSPLIT; s++) {
        const float4* p = (const float4*)(g_part + (size_t)(s * 32 + m) * (dK * dE));
        float4 v = p[r];
        sum.x += v.x; sum.y += v.y; sum.z += v.z; sum.w += v.w;
    }
    float b = (m < 16) ? Eb[m * dK + j] : Fb[(m - 16) * dK + j];
    sum.x += b; sum.y += b; sum.z += b; sum.w += b;
    float4* outp = (m < 16) ? (float4*)(g_kp + (size_t)m * (dK * dE))
                            : (float4*)(g_vp + (size_t)(m - 16) * (dK * dE));
    outp[r] = rnd4(sum);
}

// ======================= Kernel B3: kp/vp -> fragment layouts ===============
__global__ void __launch_bounds__(256, 1)
kB3()
{
    int idx = blockIdx.x * 256 + threadIdx.x;    // 131072 threads
    if (idx < 65536) {
        int h = idx >> 12, s = idx & 4095;
        int nt = s >> 7, r = s & 127;
        int kb = r >> 5, r2 = r & 31, g = r2 >> 2, t = r2 & 3;
        int j = nt * 8 + g, c = kb * 16 + t;
        const float* src = g_kp + (size_t)h * 16384 + (size_t)j * 64 + c;
        float4 v = { src[0], src[4], src[8], src[12] };
        ((float4*)g_kp2)[idx] = v;
    } else {
        int i2 = idx - 65536;
        int h = i2 >> 12, s = i2 & 4095;
        int et = s >> 9, r = s & 511;
        int jb = r >> 5, r2 = r & 31, g = r2 >> 2, t = r2 & 3;
        int e = et * 8 + g, jb16 = jb * 16;
        const float* base = g_vp + (size_t)h * 16384;
        float4 v = { base[(size_t)(jb16 + 2 * t) * 64 + e],
                     base[(size_t)(jb16 + 2 * t + 1) * 64 + e],
                     base[(size_t)(jb16 + 8 + 2 * t) * 64 + e],
                     base[(size_t)(jb16 + 9 + 2 * t) * 64 + e] };
        ((float4*)g_vp2)[i2] = v;
    }
}

// ======================= Kernel C: multi-tile register attention ============
#define C3_QS     (128 * 68)              // one q buffer (floats)
#define C3_KP     (2 * C3_QS)             // 17408
#define C3_VP     (C3_KP + 16384)
#define C3_FLOATS (C3_VP + 16384)         // 50176 floats = 200704 B
#define C3_BYTES  (C3_FLOATS * 4u)
__global__ void __launch_bounds__(256, 1)
kC()
{
    extern __shared__ float sm[];
    float* qsA = sm;                 // [128][68] buffer 0
    float* qsB = sm + C3_QS;         // [128][68] buffer 1
    float* kp2 = sm + C3_KP;         // 16384 floats
    float* vp2 = sm + C3_VP;         // 16384 floats

    const int tid = threadIdx.x;
    const int h = blockIdx.y;
    const int base_tile = blockIdx.x * 4;

    auto load_q = [&](float* dst, int tile) {
        int n0 = (base_tile + tile) * 128;
#pragma unroll
        for (int i = 0; i < 8; i++) {
            int e = tid + i * 256;
            int row = e >> 4, q = e & 15;
            cpa(dst + row * 68 + q * 4, g_qkv + (size_t)(n0 + row) * QKV_LD + h * 64 + q * 4);
        }
        CP_COMMIT();
    };

    load_q(qsA, 0);                                  // group 0
#pragma unroll
    for (int i = 0; i < 16; i++) {
        int e = tid + i * 256;
        cpa(kp2 + e * 4, g_kp2 + (size_t)h * 16384 + e * 4);
    }
#pragma unroll
    for (int i = 0; i < 16; i++) {
        int e = tid + i * 256;
        cpa(vp2 + e * 4, g_vp2 + (size_t)h * 16384 + e * 4);
    }
    CP_COMMIT();                                     // group 1
    load_q(qsB, 1);                                  // group 2

    const int lane = tid & 31, w = tid >> 5;
    const int g = lane >> 2, t = lane & 3;

    for (int it = 0; it < 4; it++) {
        if (it == 3) { CP_WAIT(0); } else { CP_WAIT(1); }
        __syncthreads();
        float* qs = (it & 1) ? qsB : qsA;
        const int n0 = (base_tile + it) * 128;

        float att[32][4];
#pragma unroll
        for (int nt = 0; nt < 32; nt++)
#pragma unroll
            for (int c = 0; c < 4; c++) att[nt][c] = 0.f;

        const float* qbase = qs + (w * 16 + g) * 68;
#pragma unroll
        for (int kb = 0; kb < 4; kb++) {
            uint32_t a[2][4];
#pragma unroll
            for (int ks2 = 0; ks2 < 2; ks2++) {
                const float* ap = qbase + kb * 16 + ks2 * 8 + t;
                a[ks2][0] = __float_as_uint(ap[0]);
                a[ks2][1] = __float_as_uint(ap[8 * 68]);
                a[ks2][2] = __float_as_uint(ap[4]);
                a[ks2][3] = __float_as_uint(ap[8 * 68 + 4]);
            }
#pragma unroll
            for (int nt = 0; nt < 32; nt++) {
                uint4 bv = *(const uint4*)(kp2 + (size_t)(nt * 128 + kb * 32 + g * 4 + t) * 4);
                mma_m16n8k8(att[nt], a[0][0], a[0][1], a[0][2], a[0][3], bv.x, bv.y);
                mma_m16n8k8(att[nt], a[1][0], a[1][1], a[1][2], a[1][3], bv.z, bv.w);
            }
        }

        __syncthreads();
        if (it + 2 < 4) load_q(qs, it + 2);

        float mx0 = -1e30f, mx1 = -1e30f;
#pragma unroll
        for (int nt = 0; nt < 32; nt++) {
            att[nt][0] *= 0.125f; att[nt][1] *= 0.125f;
            att[nt][2] *= 0.125f; att[nt][3] *= 0.125f;
            mx0 = fmaxf(mx0, fmaxf(att[nt][0], att[nt][1]));
            mx1 = fmaxf(mx1, fmaxf(att[nt][2], att[nt][3]));
        }
        mx0 = fmaxf(mx0, __shfl_xor_sync(0xffffffffu, mx0, 1));
        mx0 = fmaxf(mx0, __shfl_xor_sync(0xffffffffu, mx0, 2));
        mx1 = fmaxf(mx1, __shfl_xor_sync(0xffffffffu, mx1, 1));
        mx1 = fmaxf(mx1, __shfl_xor_sync(0xffffffffu, mx1, 2));

        float s0 = 0.f, s1 = 0.f;
#pragma unroll
        for (int nt = 0; nt < 32; nt++) {
            float v0 = __expf(att[nt][0] - mx0);
            float v1 = __expf(att[nt][1] - mx0);
            float v2 = __expf(att[nt][2] - mx1);
            float v3 = __expf(att[nt][3] - mx1);
            att[nt][0] = v0; att[nt][1] = v1; att[nt][2] = v2; att[nt][3] = v3;
            s0 += v0 + v1; s1 += v2 + v3;
        }
        s0 += __shfl_xor_sync(0xffffffffu, s0, 1);
        s0 += __shfl_xor_sync(0xffffffffu, s0, 2);
        s1 += __shfl_xor_sync(0xffffffffu, s1, 1);
        s1 += __shfl_xor_sync(0xffffffffu, s1, 2);
        const float inv0 = 1.f / s0, inv1 = 1.f / s1;
#pragma unroll
        for (int nt = 0; nt < 32; nt++) {
            att[nt][0] = rndf(att[nt][0] * inv0);
            att[nt][1] = rndf(att[nt][1] * inv0);
            att[nt][2] = rndf(att[nt][2] * inv1);
            att[nt][3] = rndf(att[nt][3] * inv1);
        }

        float zacc[8][4];
#pragma unroll
        for (int et = 0; et < 8; et++)
#pragma unroll
            for (int c = 0; c < 4; c++) zacc[et][c] = 0.f;

#pragma unroll
        for (int jb = 0; jb < 16; jb++) {
            uint32_t aA0 = __float_as_uint(att[2 * jb][0]);
            uint32_t aA1 = __float_as_uint(att[2 * jb][2]);
            uint32_t aA2 = __float_as_uint(att[2 * jb][1]);
            uint32_t aA3 = __float_as_uint(att[2 * jb][3]);
            uint32_t aB0 = __float_as_uint(att[2 * jb + 1][0]);
            uint32_t aB1 = __float_as_uint(att[2 * jb + 1][2]);
            uint32_t aB2 = __float_as_uint(att[2 * jb + 1][1]);
            uint32_t aB3 = __float_as_uint(att[2 * jb + 1][3]);
#pragma unroll
            for (int et = 0; et < 8; et++) {
                uint4 bv = *(const uint4*)(vp2 + (size_t)(et * 512 + jb * 32 + g * 4 + t) * 4);
                mma_m16n8k8(zacc[et], aA0, aA1, aA2, aA3, bv.x, bv.y);
                mma_m16n8k8(zacc[et], aB0, aB1, aB2, aB3, bv.z, bv.w);
            }
        }

        const int row = n0 + w * 16 + g;
#pragma unroll
        for (int et = 0; et < 8; et++) {
            int col = h * 64 + et * 8 + 2 * t;
            float2 v0 = { rndf(zacc[et][0]), rndf(zacc[et][1]) };
            float2 v1 = { rndf(zacc[et][2]), rndf(zacc[et][3]) };
            *(float2*)&g_z[(size_t)row * (dH * dE) + col] = v0;
            *(float2*)&g_z[(size_t)(row + 8) * (dH * dE) + col] = v1;
        }
    }
}

// ======================= Kernel D: output projection ========================
#define D_SMEM_BYTES ((2u * 128u * 36u + 2u * 64u * 36u) * 4u)
__global__ void __launch_bounds__(256, 1)
kD(float* __restrict__ out)
{
    extern __shared__ float sm[];
    float* Zs = sm;                  // [2][128][36]
    float* Ws = sm + 2 * 128 * 36;   // [2][64][36]
    const int tid = threadIdx.x;
    const int n0 = blockIdx.x * 128;

    auto load_tile = [&](int buf, int kb) {
        float* dZ = Zs + buf * 128 * 36;
        float* dW = Ws + buf * 64 * 36;
#pragma unroll
        for (int i = 0; i < 4; i++) {
            int e = tid + i * 256;
            int row = e >> 3, q = e & 7;
            cpa(dZ + row * 36 + q * 4, g_z + (size_t)(n0 + row) * (dH * dE) + kb + q * 4);
        }
#pragma unroll
        for (int i = 0; i < 2; i++) {
            int e = tid + i * 256;
            int row = e >> 3, q = e & 7;
            cpa(dW + row * 36 + q * 4, g_wo32 + (size_t)row * (dH * dE) + kb + q * 4);
        }
    };

    const int lane = tid & 31, w = tid >> 5;
    const int g = lane >> 2, t = lane & 3;
    const int wr = w >> 2, wc = w & 3;   // 2x4 warp grid, warp tile 64x16

    float acc[4][2][4];
#pragma unroll
    for (int a = 0; a < 4; a++)
#pragma unroll
        for (int b = 0; b < 2; b++)
#pragma unroll
            for (int c = 0; c < 4; c++) acc[a][b][c] = 0.f;

    load_tile(0, 0);
    CP_COMMIT();
    const int NKT = (dH * dE) / 32;
    for (int kt = 0; kt < NKT; kt++) {
        if (kt + 1 < NKT) { load_tile((kt + 1) & 1, (kt + 1) * 32); CP_COMMIT(); CP_WAIT(1); }
        else              { CP_WAIT(0); }
        __syncthreads();
        const float* Z = Zs + (kt & 1) * 128 * 36;
        const float* W2 = Ws + (kt & 1) * 64 * 36;
#pragma unroll
        for (int ks = 0; ks < 4; ks++) {
            const int k = ks * 8;
            uint32_t af[4][4];
#pragma unroll
            for (int mt = 0; mt < 4; mt++) {
                const float* ap = Z + (wr * 64 + mt * 16 + g) * 36 + k + t;
                af[mt][0] = __float_as_uint(ap[0]);
                af[mt][1] = __float_as_uint(ap[8 * 36]);
                af[mt][2] = __float_as_uint(ap[4]);
                af[mt][3] = __float_as_uint(ap[8 * 36 + 4]);
            }
#pragma unroll
            for (int nt = 0; nt < 2; nt++) {
                const float* bp = W2 + (wc * 16 + nt * 8 + g) * 36 + k + t;
                uint32_t b0 = __float_as_uint(bp[0]);
                uint32_t b1 = __float_as_uint(bp[4]);
#pragma unroll
                for (int mt = 0; mt < 4; mt++)
                    mma_m16n8k8(acc[mt][nt], af[mt][0], af[mt][1], af[mt][2], af[mt][3], b0, b1);
            }
        }
        __syncthreads();
    }

#pragma unroll
    for (int mt = 0; mt < 4; mt++)
#pragma unroll
        for (int nt = 0; nt < 2; nt++) {
            int row = n0 + wr * 64 + mt * 16 + g;
            int col = wc * 16 + nt * 8 + 2 * t;
            float2 v0 = { acc[mt][nt][0], acc[mt][nt][1] };
            float2 v1 = { acc[mt][nt][2], acc[mt][nt][3] };
            *(float2*)&out[(size_t)row * dE + col] = v0;
            *(float2*)&out[(size_t)(row + 8) * dE + col] = v1;
        }
}

// ======================= launcher ===========================================
extern "C" void kernel_launch(void* const* d_in, const int* in_sizes, int n_in,
                              void* d_out, int out_size)
{
    const float* x  = (const float*)d_in[0];
    const float* Wq = (const float*)d_in[1];
    const float* bq = (const float*)d_in[2];
    const float* Wk = (const float*)d_in[3];
    const float* bk = (const float*)d_in[4];
    const float* Wv = (const float*)d_in[5];
    const float* bv = (const float*)d_in[6];
    const float* Ew = (const float*)d_in[7];
    const float* Eb = (const float*)d_in[8];
    const float* Fw = (const float*)d_in[9];
    const float* Fb = (const float*)d_in[10];
    const float* Wo = (const float*)d_in[11];
    float* out = (float*)d_out;

    cudaFuncSetAttribute(kA, cudaFuncAttributeMaxDynamicSharedMemorySize, KA_SMEM);
    cudaFuncSetAttribute(kB, cudaFuncAttributeMaxDynamicSharedMemorySize, B_SMEM_BYTES);
    cudaFuncSetAttribute(kC, cudaFuncAttributeMaxDynamicSharedMemorySize, C3_BYTES);
    cudaFuncSetAttribute(kD, cudaFuncAttributeMaxDynamicSharedMemorySize, D_SMEM_BYTES);

    kPre<<<7235, 256>>>(x, Wq, Wk, Wv, bq, bk, bv, Wo);
    kA<<<dim3(24, 32), 256, KA_SMEM>>>();
    kB<<<dim3(NSPLIT, 64), 256, B_SMEM_BYTES>>>(Ew, Fw);
    kB2<<<512, 256>>>(Eb, Fb);
    kB3<<<512, 256>>>();
    kC<<<dim3(8, 16), 256, C3_BYTES>>>();
    kD<<<32, 256, D_SMEM_BYTES>>>(out);
}

// round 16
// speedup vs baseline: 1.0078x; 1.0078x over previous
#include <cuda_runtime.h>
#include <cstdint>

#define dH 16
#define dD 1024
#define dE 64
#define dN 4096
#define dK 256
#define QKV_LD 3072
#define NSPLIT 8

// ---------------- scratch (static device globals: allocation-free) ----------
__device__ float g_qkv[(size_t)dN * QKV_LD];            // (N, 3*H*E): q|k|v (tf32-rounded)
__device__ float g_part[(size_t)NSPLIT * 32 * dK * dE]; // split-K partials for kp/vp
__device__ float g_kp[(size_t)dH * dK * dE];            // (H, K, E) rounded
__device__ float g_vp[(size_t)dH * dK * dE];            // (H, K, E) rounded
__device__ float g_kp2[(size_t)dH * dK * dE];           // kp B-fragment-vector layout
__device__ float g_vp2[(size_t)dH * dK * dE];           // vp pi-permuted B-frag layout
__device__ float g_z[(size_t)dN * (dH * dE)];           // (N, H*E) rounded
__device__ float g_x32[(size_t)dN * dD];                // X rounded + fragment-permuted
__device__ float g_w32[(size_t)3 * 1024 * dD];          // [Wq;Wk;Wv] rounded + permuted
__device__ float g_b32[3072];                           // [bq|bk|bv] (fp32)
__device__ float g_wo32[(size_t)dE * 1024];             // Wo rounded (64 x 1024 row-major)

// ---------------- helpers ---------------------------------------------------
static __device__ __forceinline__ uint32_t f2tf(float x) {
    uint32_t u;
    asm("cvt.rna.tf32.f32 %0, %1;" : "=r"(u) : "f"(x));
    return u;
}
static __device__ __forceinline__ float rndf(float x) { return __uint_as_float(f2tf(x)); }
static __device__ __forceinline__ float4 rnd4(float4 v) {
    v.x = rndf(v.x); v.y = rndf(v.y); v.z = rndf(v.z); v.w = rndf(v.w);
    return v;
}

static __device__ __forceinline__ void mma_m16n8k8(float c[4],
        uint32_t a0, uint32_t a1, uint32_t a2, uint32_t a3,
        uint32_t b0, uint32_t b1) {
    asm volatile(
        "mma.sync.aligned.m16n8k8.row.col.f32.tf32.tf32.f32 "
        "{%0,%1,%2,%3}, {%4,%5,%6,%7}, {%8,%9}, {%0,%1,%2,%3};\n"
        : "+f"(c[0]), "+f"(c[1]), "+f"(c[2]), "+f"(c[3])
        : "r"(a0), "r"(a1), "r"(a2), "r"(a3), "r"(b0), "r"(b1));
}

static __device__ __forceinline__ void cpa(float* s, const float* g) {
    uint32_t sa = (uint32_t)__cvta_generic_to_shared(s);
    asm volatile("cp.async.cg.shared.global [%0], [%1], 16;\n" :: "r"(sa), "l"(g));
}
static __device__ __forceinline__ void cpa_u(uint32_t sa, const float* g) {
    asm volatile("cp.async.cg.shared.global [%0], [%1], 16;\n" :: "r"(sa), "l"(g));
}
#define CP_COMMIT() asm volatile("cp.async.commit_group;\n")
#define CP_WAIT(n)  asm volatile("cp.async.wait_group %0;\n" :: "n"(n))

// ======================= Kernel Pre: round + permute ========================
__global__ void __launch_bounds__(256, 1)
kPre(const float* __restrict__ X,
     const float* __restrict__ Wq, const float* __restrict__ Wk, const float* __restrict__ Wv,
     const float* __restrict__ bq, const float* __restrict__ bk, const float* __restrict__ bv,
     const float* __restrict__ Wo)
{
    int i = blockIdx.x * 256 + threadIdx.x;
    if (i < 1048576) {               // ---- X permute (1M float4)
        int blk = i >> 10, w = i & 1023;
        int mb = blk >> 5, kb = blk & 31;
        int t = w & 3, g = (w >> 2) & 7, ks = (w >> 5) & 3, mt = (w >> 7) & 3, wr = (w >> 9) & 1;
        int row = mb * 128 + wr * 64 + mt * 16 + g;
        int col = kb * 32 + ks * 8 + t;
        const float* xr0 = X + (size_t)row * dD;
        const float* xr1 = xr0 + 8 * dD;
        float4 v = { xr0[col], xr1[col], xr0[col + 4], xr1[col + 4] };
        ((float4*)g_x32)[i] = rnd4(v);
        return;
    }
    int j = i - 1048576;
    if (j < 786432) {                // ---- W permute (768K float4)
        int blk = j >> 10, w = j & 1023;
        int nb = blk >> 5, kb = blk & 31;
        int t = w & 3, g = (w >> 2) & 7, kp = (w >> 5) & 1, nt = (w >> 6) & 3, wc = (w >> 8) & 3;
        int n = nb * 128 + wc * 32 + nt * 8 + g;
        int col = kb * 32 + kp * 16 + t;
        const float* Wsrc = (n < 1024) ? (Wq + (size_t)n * dD)
                          : (n < 2048) ? (Wk + (size_t)(n - 1024) * dD)
                                       : (Wv + (size_t)(n - 2048) * dD);
        float4 v = { Wsrc[col], Wsrc[col + 4], Wsrc[col + 8], Wsrc[col + 12] };
        ((float4*)g_w32)[j] = rnd4(v);
        return;
    }
    int k2 = j - 786432;
    if (k2 < 16384) {                // ---- Wo round: 64*1024 floats = 16384 float4
        ((float4*)g_wo32)[k2] = rnd4(((const float4*)Wo)[k2]);
        return;
    }
    int b = k2 - 16384;              // ---- biases (0..767 float4)
    if (b < 768) {
        const float4* src = (b < 256) ? ((const float4*)bq + b)
                           : (b < 512) ? ((const float4*)bk + (b - 256))
                                       : ((const float4*)bv + (b - 512));
        ((float4*)g_b32)[b] = *src;
    }
}

// ======================= Kernel A: QKV projection ===========================
#define KA_STG   3
#define KA_STGB  32768
#define KA_SMEM  (KA_STG * KA_STGB)
__global__ void __launch_bounds__(256, 2)
kA()
{
    extern __shared__ char smc[];
    const uint32_t sb = (uint32_t)__cvta_generic_to_shared(smc);
    const int tid = threadIdx.x, wid = tid >> 5, lane = tid & 31;
    const int g = lane >> 2, t = lane & 3;
    const int wr = wid >> 2, wc = wid & 3;     // 2x4 warp grid, warp tile 64x32
    const int nb = blockIdx.x;                 // 24 feature tiles
    const int mb = blockIdx.y;                 // 32 sequence tiles

    auto load_stage = [&](int s, int kt) {
        const float* srcA = g_x32 + (size_t)(mb * 32 + kt) * 4096;
        const float* srcB = g_w32 + (size_t)(nb * 32 + kt) * 4096;
        const uint32_t dA = sb + s * KA_STGB;
        const uint32_t dB = dA + 16384;
#pragma unroll
        for (int i = 0; i < 4; i++) cpa_u(dA + (tid + i * 256) * 16, srcA + (tid + i * 256) * 4);
#pragma unroll
        for (int i = 0; i < 4; i++) cpa_u(dB + (tid + i * 256) * 16, srcB + (tid + i * 256) * 4);
        CP_COMMIT();
    };

    float acc[4][4][4];
#pragma unroll
    for (int a = 0; a < 4; a++)
#pragma unroll
        for (int b = 0; b < 4; b++)
#pragma unroll
            for (int c = 0; c < 4; c++) acc[a][b][c] = 0.f;

    load_stage(0, 0);
    load_stage(1, 1);

    for (int kt = 0; kt < 32; kt++) {
        const int s = kt % KA_STG;
        if (kt + 2 < 32) { load_stage((kt + 2) % KA_STG, kt + 2); CP_WAIT(2); }
        else if (kt == 30) { CP_WAIT(1); }
        else               { CP_WAIT(0); }
        __syncthreads();

        const char* sA = smc + s * KA_STGB + (size_t)(wr * 512 + g * 4 + t) * 16;
        const char* sB = smc + s * KA_STGB + 16384 + (size_t)(wc * 256 + g * 4 + t) * 16;
#pragma unroll
        for (int kp = 0; kp < 2; kp++) {
            uint4 bv[4];
#pragma unroll
            for (int nt = 0; nt < 4; nt++)
                bv[nt] = *(const uint4*)(sB + (size_t)(nt * 64 + kp * 32) * 16);
#pragma unroll
            for (int ki = 0; ki < 2; ki++) {
                const int ks = kp * 2 + ki;
                uint4 av[4];
#pragma unroll
                for (int mt = 0; mt < 4; mt++)
                    av[mt] = *(const uint4*)(sA + (size_t)(mt * 128 + ks * 32) * 16);
#pragma unroll
                for (int nt = 0; nt < 4; nt++) {
                    uint32_t b0 = ki ? bv[nt].z : bv[nt].x;
                    uint32_t b1 = ki ? bv[nt].w : bv[nt].y;
#pragma unroll
                    for (int mt = 0; mt < 4; mt++)
                        mma_m16n8k8(acc[mt][nt], av[mt].x, av[mt].y, av[mt].z, av[mt].w, b0, b1);
                }
            }
        }
        __syncthreads();
    }

    const int r0 = nb * 128, m0 = mb * 128;
#pragma unroll
    for (int mt = 0; mt < 4; mt++) {
#pragma unroll
        for (int nt = 0; nt < 4; nt++) {
            int row = m0 + wr * 64 + mt * 16 + g;
            int col = r0 + wc * 32 + nt * 8 + 2 * t;
            float b0 = g_b32[col], b1 = g_b32[col + 1];
            float2 v0 = { rndf(acc[mt][nt][0] + b0), rndf(acc[mt][nt][1] + b1) };
            float2 v1 = { rndf(acc[mt][nt][2] + b0), rndf(acc[mt][nt][3] + b1) };
            *(float2*)&g_qkv[(size_t)row * QKV_LD + col] = v0;
            *(float2*)&g_qkv[(size_t)(row + 8) * QKV_LD + col] = v1;
        }
    }
}

// ======================= Kernel B: kp/vp (split-K=8, occ 2) =================
#define B_SMEM_BYTES ((2u * 256u * 36u + 2u * 32u * 72u) * 4u)
__global__ void __launch_bounds__(256, 2)
kB(const float* __restrict__ Ew, const float* __restrict__ Fw)
{
    extern __shared__ float sm[];
    float* As = sm;                   // [2][256][36]
    float* Bs = sm + 2 * 256 * 36;    // [2][32][72]
    const int tid = threadIdx.x;
    const int s = blockIdx.x;         // ksplit 0..7
    const int m = blockIdx.y;         // matrix 0..31
    const float* Aw = (m < 16) ? (Ew + (size_t)m * dK * dN)
                               : (Fw + (size_t)(m - 16) * dK * dN);
    const int cbase = (m < 16) ? (1024 + m * 64) : (2048 + (m - 16) * 64);
    const int kbase0 = s * 512;

    auto load_tile = [&](int buf, int kb) {
        float* dA = As + buf * 256 * 36;
        float* dB = Bs + buf * 32 * 72;
#pragma unroll
        for (int i = 0; i < 8; i++) {
            int e = tid + i * 256;
            int row = e >> 3, q = e & 7;
            cpa(dA + row * 36 + q * 4, Aw + (size_t)row * dN + kb + q * 4);
        }
#pragma unroll
        for (int i = 0; i < 2; i++) {
            int e = tid + i * 256;
            int row = e >> 4, q = e & 15;
            cpa(dB + row * 72 + q * 4, g_qkv + (size_t)(kb + row) * QKV_LD + cbase + q * 4);
        }
    };

    const int lane = tid & 31, w = tid >> 5;
    const int g = lane >> 2, t = lane & 3;
    const int wr = w >> 1, wc = w & 1;   // 4x2 warp grid, warp tile 64x32

    float acc[4][4][4];
#pragma unroll
    for (int a = 0; a < 4; a++)
#pragma unroll
        for (int b = 0; b < 4; b++)
#pragma unroll
            for (int c = 0; c < 4; c++) acc[a][b][c] = 0.f;

    load_tile(0, kbase0);
    CP_COMMIT();
    const int NKT = 512 / 32;
    for (int kt = 0; kt < NKT; kt++) {
        if (kt + 1 < NKT) { load_tile((kt + 1) & 1, kbase0 + (kt + 1) * 32); CP_COMMIT(); CP_WAIT(1); }
        else              { CP_WAIT(0); }
        __syncthreads();
        const float* A = As + (kt & 1) * 256 * 36;
        const float* B = Bs + (kt & 1) * 32 * 72;
#pragma unroll
        for (int ks = 0; ks < 4; ks++) {
            const int k = ks * 8;
            uint32_t af[4][4];
#pragma unroll
            for (int mt = 0; mt < 4; mt++) {
                const float* ap = A + (wr * 64 + mt * 16 + g) * 36 + k + t;
                af[mt][0] = f2tf(ap[0]);
                af[mt][1] = f2tf(ap[8 * 36]);
                af[mt][2] = f2tf(ap[4]);
                af[mt][3] = f2tf(ap[8 * 36 + 4]);
            }
#pragma unroll
            for (int nt = 0; nt < 4; nt++) {
                const int col = wc * 32 + nt * 8 + g;
                uint32_t b0 = __float_as_uint(B[(k + t) * 72 + col]);       // pre-rounded
                uint32_t b1 = __float_as_uint(B[(k + t + 4) * 72 + col]);
#pragma unroll
                for (int mt = 0; mt < 4; mt++)
                    mma_m16n8k8(acc[mt][nt], af[mt][0], af[mt][1], af[mt][2], af[mt][3], b0, b1);
            }
        }
        __syncthreads();
    }

    float* base = g_part + (size_t)(s * 32 + m) * (dK * dE);
#pragma unroll
    for (int mt = 0; mt < 4; mt++) {
#pragma unroll
        for (int nt = 0; nt < 4; nt++) {
            int j = wr * 64 + mt * 16 + g;
            int e = wc * 32 + nt * 8 + 2 * t;
            float2 v0 = { acc[mt][nt][0], acc[mt][nt][1] };
            float2 v1 = { acc[mt][nt][2], acc[mt][nt][3] };
            *(float2*)&base[(size_t)j * dE + e] = v0;
            *(float2*)&base[(size_t)(j + 8) * dE + e] = v1;
        }
    }
}

// ======================= Kernel B2: split-K reduce + bias + round ===========
__global__ void __launch_bounds__(256, 1)
kB2(const float* __restrict__ Eb, const float* __restrict__ Fb)
{
    int idx = blockIdx.x * 256 + threadIdx.x;    // float4 index, 131072 total
    int m = idx >> 12;
    int r = idx & 4095;
    int j = r >> 4;
    float4 sum = make_float4(0.f, 0.f, 0.f, 0.f);
#pragma unroll
    for (int s = 0; s < NSPLIT; s++) {
        const float4* p = (const float4*)(g_part + (size_t)(s * 32 + m) * (dK * dE));
        float4 v = p[r];
        sum.x += v.x; sum.y += v.y; sum.z += v.z; sum.w += v.w;
    }
    float b = (m < 16) ? Eb[m * dK + j] : Fb[(m - 16) * dK + j];
    sum.x += b; sum.y += b; sum.z += b; sum.w += b;
    float4* outp = (m < 16) ? (float4*)(g_kp + (size_t)m * (dK * dE))
                            : (float4*)(g_vp + (size_t)(m - 16) * (dK * dE));
    outp[r] = rnd4(sum);
}

// ======================= Kernel B3: kp/vp -> fragment layouts ===============
__global__ void __launch_bounds__(256, 1)
kB3()
{
    int idx = blockIdx.x * 256 + threadIdx.x;    // 131072 threads
    if (idx < 65536) {
        int h = idx >> 12, s = idx & 4095;
        int nt = s >> 7, r = s & 127;
        int kb = r >> 5, r2 = r & 31, g = r2 >> 2, t = r2 & 3;
        int j = nt * 8 + g, c = kb * 16 + t;
        const float* src = g_kp + (size_t)h * 16384 + (size_t)j * 64 + c;
        float4 v = { src[0], src[4], src[8], src[12] };
        ((float4*)g_kp2)[idx] = v;
    } else {
        int i2 = idx - 65536;
        int h = i2 >> 12, s = i2 & 4095;
        int et = s >> 9, r = s & 511;
        int jb = r >> 5, r2 = r & 31, g = r2 >> 2, t = r2 & 3;
        int e = et * 8 + g, jb16 = jb * 16;
        const float* base = g_vp + (size_t)h * 16384;
        float4 v = { base[(size_t)(jb16 + 2 * t) * 64 + e],
                     base[(size_t)(jb16 + 2 * t + 1) * 64 + e],
                     base[(size_t)(jb16 + 8 + 2 * t) * 64 + e],
                     base[(size_t)(jb16 + 9 + 2 * t) * 64 + e] };
        ((float4*)g_vp2)[i2] = v;
    }
}

// ======================= Kernel C: multi-tile register attention ============
#define C3_QS     (128 * 68)              // one q buffer (floats)
#define C3_KP     (2 * C3_QS)             // 17408
#define C3_VP     (C3_KP + 16384)
#define C3_FLOATS (C3_VP + 16384)         // 50176 floats = 200704 B
#define C3_BYTES  (C3_FLOATS * 4u)
__global__ void __launch_bounds__(256, 1)
kC()
{
    extern __shared__ float sm[];
    float* qsA = sm;                 // [128][68] buffer 0
    float* qsB = sm + C3_QS;         // [128][68] buffer 1
    float* kp2 = sm + C3_KP;         // 16384 floats
    float* vp2 = sm + C3_VP;         // 16384 floats

    const int tid = threadIdx.x;
    const int h = blockIdx.y;
    const int base_tile = blockIdx.x * 4;

    auto load_q = [&](float* dst, int tile) {
        int n0 = (base_tile + tile) * 128;
#pragma unroll
        for (int i = 0; i < 8; i++) {
            int e = tid + i * 256;
            int row = e >> 4, q = e & 15;
            cpa(dst + row * 68 + q * 4, g_qkv + (size_t)(n0 + row) * QKV_LD + h * 64 + q * 4);
        }
        CP_COMMIT();
    };

    load_q(qsA, 0);                                  // group 0
#pragma unroll
    for (int i = 0; i < 16; i++) {
        int e = tid + i * 256;
        cpa(kp2 + e * 4, g_kp2 + (size_t)h * 16384 + e * 4);
    }
#pragma unroll
    for (int i = 0; i < 16; i++) {
        int e = tid + i * 256;
        cpa(vp2 + e * 4, g_vp2 + (size_t)h * 16384 + e * 4);
    }
    CP_COMMIT();                                     // group 1
    load_q(qsB, 1);                                  // group 2

    const int lane = tid & 31, w = tid >> 5;
    const int g = lane >> 2, t = lane & 3;

    for (int it = 0; it < 4; it++) {
        if (it == 3) { CP_WAIT(0); } else { CP_WAIT(1); }
        __syncthreads();
        float* qs = (it & 1) ? qsB : qsA;
        const int n0 = (base_tile + it) * 128;

        float att[32][4];
#pragma unroll
        for (int nt = 0; nt < 32; nt++)
#pragma unroll
            for (int c = 0; c < 4; c++) att[nt][c] = 0.f;

        const float* qbase = qs + (w * 16 + g) * 68;
#pragma unroll
        for (int kb = 0; kb < 4; kb++) {
            uint32_t a[2][4];
#pragma unroll
            for (int ks2 = 0; ks2 < 2; ks2++) {
                const float* ap = qbase + kb * 16 + ks2 * 8 + t;
                a[ks2][0] = __float_as_uint(ap[0]);
                a[ks2][1] = __float_as_uint(ap[8 * 68]);
                a[ks2][2] = __float_as_uint(ap[4]);
                a[ks2][3] = __float_as_uint(ap[8 * 68 + 4]);
            }
#pragma unroll
            for (int nt = 0; nt < 32; nt++) {
                uint4 bv = *(const uint4*)(kp2 + (size_t)(nt * 128 + kb * 32 + g * 4 + t) * 4);
                mma_m16n8k8(att[nt], a[0][0], a[0][1], a[0][2], a[0][3], bv.x, bv.y);
                mma_m16n8k8(att[nt], a[1][0], a[1][1], a[1][2], a[1][3], bv.z, bv.w);
            }
        }

        __syncthreads();
        if (it + 2 < 4) load_q(qs, it + 2);

        float mx0 = -1e30f, mx1 = -1e30f;
#pragma unroll
        for (int nt = 0; nt < 32; nt++) {
            att[nt][0] *= 0.125f; att[nt][1] *= 0.125f;
            att[nt][2] *= 0.125f; att[nt][3] *= 0.125f;
            mx0 = fmaxf(mx0, fmaxf(att[nt][0], att[nt][1]));
            mx1 = fmaxf(mx1, fmaxf(att[nt][2], att[nt][3]));
        }
        mx0 = fmaxf(mx0, __shfl_xor_sync(0xffffffffu, mx0, 1));
        mx0 = fmaxf(mx0, __shfl_xor_sync(0xffffffffu, mx0, 2));
        mx1 = fmaxf(mx1, __shfl_xor_sync(0xffffffffu, mx1, 1));
        mx1 = fmaxf(mx1, __shfl_xor_sync(0xffffffffu, mx1, 2));

        float s0 = 0.f, s1 = 0.f;
#pragma unroll
        for (int nt = 0; nt < 32; nt++) {
            float v0 = __expf(att[nt][0] - mx0);
            float v1 = __expf(att[nt][1] - mx0);
            float v2 = __expf(att[nt][2] - mx1);
            float v3 = __expf(att[nt][3] - mx1);
            att[nt][0] = v0; att[nt][1] = v1; att[nt][2] = v2; att[nt][3] = v3;
            s0 += v0 + v1; s1 += v2 + v3;
        }
        s0 += __shfl_xor_sync(0xffffffffu, s0, 1);
        s0 += __shfl_xor_sync(0xffffffffu, s0, 2);
        s1 += __shfl_xor_sync(0xffffffffu, s1, 1);
        s1 += __shfl_xor_sync(0xffffffffu, s1, 2);
        const float inv0 = 1.f / s0, inv1 = 1.f / s1;
#pragma unroll
        for (int nt = 0; nt < 32; nt++) {
            att[nt][0] = rndf(att[nt][0] * inv0);
            att[nt][1] = rndf(att[nt][1] * inv0);
            att[nt][2] = rndf(att[nt][2] * inv1);
            att[nt][3] = rndf(att[nt][3] * inv1);
        }

        float zacc[8][4];
#pragma unroll
        for (int et = 0; et < 8; et++)
#pragma unroll
            for (int c = 0; c < 4; c++) zacc[et][c] = 0.f;

#pragma unroll
        for (int jb = 0; jb < 16; jb++) {
            uint32_t aA0 = __float_as_uint(att[2 * jb][0]);
            uint32_t aA1 = __float_as_uint(att[2 * jb][2]);
            uint32_t aA2 = __float_as_uint(att[2 * jb][1]);
            uint32_t aA3 = __float_as_uint(att[2 * jb][3]);
            uint32_t aB0 = __float_as_uint(att[2 * jb + 1][0]);
            uint32_t aB1 = __float_as_uint(att[2 * jb + 1][2]);
            uint32_t aB2 = __float_as_uint(att[2 * jb + 1][1]);
            uint32_t aB3 = __float_as_uint(att[2 * jb + 1][3]);
#pragma unroll
            for (int et = 0; et < 8; et++) {
                uint4 bv = *(const uint4*)(vp2 + (size_t)(et * 512 + jb * 32 + g * 4 + t) * 4);
                mma_m16n8k8(zacc[et], aA0, aA1, aA2, aA3, bv.x, bv.y);
                mma_m16n8k8(zacc[et], aB0, aB1, aB2, aB3, bv.z, bv.w);
            }
        }

        const int row = n0 + w * 16 + g;
#pragma unroll
        for (int et = 0; et < 8; et++) {
            int col = h * 64 + et * 8 + 2 * t;
            float2 v0 = { rndf(zacc[et][0]), rndf(zacc[et][1]) };
            float2 v1 = { rndf(zacc[et][2]), rndf(zacc[et][3]) };
            *(float2*)&g_z[(size_t)row * (dH * dE) + col] = v0;
            *(float2*)&g_z[(size_t)(row + 8) * (dH * dE) + col] = v1;
        }
    }
}

// ======================= Kernel D: output projection ========================
#define D_SMEM_BYTES ((2u * 128u * 36u + 2u * 64u * 36u) * 4u)
__global__ void __launch_bounds__(256, 1)
kD(float* __restrict__ out)
{
    extern __shared__ float sm[];
    float* Zs = sm;                  // [2][128][36]
    float* Ws = sm + 2 * 128 * 36;   // [2][64][36]
    const int tid = threadIdx.x;
    const int n0 = blockIdx.x * 128;

    auto load_tile = [&](int buf, int kb) {
        float* dZ = Zs + buf * 128 * 36;
        float* dW = Ws + buf * 64 * 36;
#pragma unroll
        for (int i = 0; i < 4; i++) {
            int e = tid + i * 256;
            int row = e >> 3, q = e & 7;
            cpa(dZ + row * 36 + q * 4, g_z + (size_t)(n0 + row) * (dH * dE) + kb + q * 4);
        }
#pragma unroll
        for (int i = 0; i < 2; i++) {
            int e = tid + i * 256;
            int row = e >> 3, q = e & 7;
            cpa(dW + row * 36 + q * 4, g_wo32 + (size_t)row * (dH * dE) + kb + q * 4);
        }
    };

    const int lane = tid & 31, w = tid >> 5;
    const int g = lane >> 2, t = lane & 3;
    const int wr = w >> 2, wc = w & 3;   // 2x4 warp grid, warp tile 64x16

    float acc[4][2][4];
#pragma unroll
    for (int a = 0; a < 4; a++)
#pragma unroll
        for (int b = 0; b < 2; b++)
#pragma unroll
            for (int c = 0; c < 4; c++) acc[a][b][c] = 0.f;

    load_tile(0, 0);
    CP_COMMIT();
    const int NKT = (dH * dE) / 32;
    for (int kt = 0; kt < NKT; kt++) {
        if (kt + 1 < NKT) { load_tile((kt + 1) & 1, (kt + 1) * 32); CP_COMMIT(); CP_WAIT(1); }
        else              { CP_WAIT(0); }
        __syncthreads();
        const float* Z = Zs + (kt & 1) * 128 * 36;
        const float* W2 = Ws + (kt & 1) * 64 * 36;
#pragma unroll
        for (int ks = 0; ks < 4; ks++) {
            const int k = ks * 8;
            uint32_t af[4][4];
#pragma unroll
            for (int mt = 0; mt < 4; mt++) {
                const float* ap = Z + (wr * 64 + mt * 16 + g) * 36 + k + t;
                af[mt][0] = __float_as_uint(ap[0]);
                af[mt][1] = __float_as_uint(ap[8 * 36]);
                af[mt][2] = __float_as_uint(ap[4]);
                af[mt][3] = __float_as_uint(ap[8 * 36 + 4]);
            }
#pragma unroll
            for (int nt = 0; nt < 2; nt++) {
                const float* bp = W2 + (wc * 16 + nt * 8 + g) * 36 + k + t;
                uint32_t b0 = __float_as_uint(bp[0]);
                uint32_t b1 = __float_as_uint(bp[4]);
#pragma unroll
                for (int mt = 0; mt < 4; mt++)
                    mma_m16n8k8(acc[mt][nt], af[mt][0], af[mt][1], af[mt][2], af[mt][3], b0, b1);
            }
        }
        __syncthreads();
    }

#pragma unroll
    for (int mt = 0; mt < 4; mt++)
#pragma unroll
        for (int nt = 0; nt < 2; nt++) {
            int row = n0 + wr * 64 + mt * 16 + g;
            int col = wc * 16 + nt * 8 + 2 * t;
            float2 v0 = { acc[mt][nt][0], acc[mt][nt][1] };
            float2 v1 = { acc[mt][nt][2], acc[mt][nt][3] };
            *(float2*)&out[(size_t)row * dE + col] = v0;
            *(float2*)&out[(size_t)(row + 8) * dE + col] = v1;
        }
}

// ======================= launcher ===========================================
extern "C" void kernel_launch(void* const* d_in, const int* in_sizes, int n_in,
                              void* d_out, int out_size)
{
    const float* x  = (const float*)d_in[0];
    const float* Wq = (const float*)d_in[1];
    const float* bq = (const float*)d_in[2];
    const float* Wk = (const float*)d_in[3];
    const float* bk = (const float*)d_in[4];
    const float* Wv = (const float*)d_in[5];
    const float* bv = (const float*)d_in[6];
    const float* Ew = (const float*)d_in[7];
    const float* Eb = (const float*)d_in[8];
    const float* Fw = (const float*)d_in[9];
    const float* Fb = (const float*)d_in[10];
    const float* Wo = (const float*)d_in[11];
    float* out = (float*)d_out;

    cudaFuncSetAttribute(kA, cudaFuncAttributeMaxDynamicSharedMemorySize, KA_SMEM);
    cudaFuncSetAttribute(kB, cudaFuncAttributeMaxDynamicSharedMemorySize, B_SMEM_BYTES);
    cudaFuncSetAttribute(kC, cudaFuncAttributeMaxDynamicSharedMemorySize, C3_BYTES);
    cudaFuncSetAttribute(kD, cudaFuncAttributeMaxDynamicSharedMemorySize, D_SMEM_BYTES);

    kPre<<<7235, 256>>>(x, Wq, Wk, Wv, bq, bk, bv, Wo);
    kA<<<dim3(24, 32), 256, KA_SMEM>>>();
    kB<<<dim3(NSPLIT, 32), 256, B_SMEM_BYTES>>>(Ew, Fw);
    kB2<<<512, 256>>>(Eb, Fb);
    kB3<<<512, 256>>>();
    kC<<<dim3(8, 16), 256, C3_BYTES>>>();
    kD<<<32, 256, D_SMEM_BYTES>>>(out);
}

// round 17
// speedup vs baseline: 1.0160x; 1.0081x over previous
#include <cuda_runtime.h>
#include <cstdint>

#define dH 16
#define dD 1024
#define dE 64
#define dN 4096
#define dK 256
#define QKV_LD 3072
#define NSPLIT 8

// ---------------- scratch (static device globals: allocation-free) ----------
__device__ float g_qkv[(size_t)dN * QKV_LD];            // (N, 3*H*E): q|k|v (tf32-rounded)
__device__ float g_part[(size_t)NSPLIT * 32 * dK * dE]; // split-K partials for kp/vp
__device__ float g_kp[(size_t)dH * dK * dE];            // (H, K, E) rounded
__device__ float g_vp[(size_t)dH * dK * dE];            // (H, K, E) rounded
__device__ float g_kp2[(size_t)dH * dK * dE];           // kp B-fragment-vector layout
__device__ float g_vp2[(size_t)dH * dK * dE];           // vp pi-permuted B-frag layout
__device__ float g_z[(size_t)dN * (dH * dE)];           // (N, H*E) rounded
__device__ float g_x32[(size_t)dN * dD];                // X rounded + fragment-permuted
__device__ float g_w32[(size_t)3 * 1024 * dD];          // [Wq;Wk;Wv] rounded + permuted
__device__ float g_b32[3072];                           // [bq|bk|bv] (fp32)
__device__ float g_wo32[(size_t)dE * 1024];             // Wo rounded (64 x 1024 row-major)

// ---------------- helpers ---------------------------------------------------
static __device__ __forceinline__ uint32_t f2tf(float x) {
    uint32_t u;
    asm("cvt.rna.tf32.f32 %0, %1;" : "=r"(u) : "f"(x));
    return u;
}
static __device__ __forceinline__ float rndf(float x) { return __uint_as_float(f2tf(x)); }
static __device__ __forceinline__ float4 rnd4(float4 v) {
    v.x = rndf(v.x); v.y = rndf(v.y); v.z = rndf(v.z); v.w = rndf(v.w);
    return v;
}

static __device__ __forceinline__ void mma_m16n8k8(float c[4],
        uint32_t a0, uint32_t a1, uint32_t a2, uint32_t a3,
        uint32_t b0, uint32_t b1) {
    asm volatile(
        "mma.sync.aligned.m16n8k8.row.col.f32.tf32.tf32.f32 "
        "{%0,%1,%2,%3}, {%4,%5,%6,%7}, {%8,%9}, {%0,%1,%2,%3};\n"
        : "+f"(c[0]), "+f"(c[1]), "+f"(c[2]), "+f"(c[3])
        : "r"(a0), "r"(a1), "r"(a2), "r"(a3), "r"(b0), "r"(b1));
}

static __device__ __forceinline__ void cpa(float* s, const float* g) {
    uint32_t sa = (uint32_t)__cvta_generic_to_shared(s);
    asm volatile("cp.async.cg.shared.global [%0], [%1], 16;\n" :: "r"(sa), "l"(g));
}
static __device__ __forceinline__ void cpa_u(uint32_t sa, const float* g) {
    asm volatile("cp.async.cg.shared.global [%0], [%1], 16;\n" :: "r"(sa), "l"(g));
}
#define CP_COMMIT() asm volatile("cp.async.commit_group;\n")
#define CP_WAIT(n)  asm volatile("cp.async.wait_group %0;\n" :: "n"(n))

// ======================= Kernel Pre: round + permute ========================
__global__ void __launch_bounds__(256, 1)
kPre(const float* __restrict__ X,
     const float* __restrict__ Wq, const float* __restrict__ Wk, const float* __restrict__ Wv,
     const float* __restrict__ bq, const float* __restrict__ bk, const float* __restrict__ bv,
     const float* __restrict__ Wo)
{
    int i = blockIdx.x * 256 + threadIdx.x;
    if (i < 1048576) {               // ---- X permute (1M float4)
        int blk = i >> 10, w = i & 1023;
        int mb = blk >> 5, kb = blk & 31;
        int t = w & 3, g = (w >> 2) & 7, ks = (w >> 5) & 3, mt = (w >> 7) & 3, wr = (w >> 9) & 1;
        int row = mb * 128 + wr * 64 + mt * 16 + g;
        int col = kb * 32 + ks * 8 + t;
        const float* xr0 = X + (size_t)row * dD;
        const float* xr1 = xr0 + 8 * dD;
        float4 v = { xr0[col], xr1[col], xr0[col + 4], xr1[col + 4] };
        ((float4*)g_x32)[i] = rnd4(v);
        return;
    }
    int j = i - 1048576;
    if (j < 786432) {                // ---- W permute (768K float4)
        int blk = j >> 10, w = j & 1023;
        int nb = blk >> 5, kb = blk & 31;
        int t = w & 3, g = (w >> 2) & 7, kp = (w >> 5) & 1, nt = (w >> 6) & 3, wc = (w >> 8) & 3;
        int n = nb * 128 + wc * 32 + nt * 8 + g;
        int col = kb * 32 + kp * 16 + t;
        const float* Wsrc = (n < 1024) ? (Wq + (size_t)n * dD)
                          : (n < 2048) ? (Wk + (size_t)(n - 1024) * dD)
                                       : (Wv + (size_t)(n - 2048) * dD);
        float4 v = { Wsrc[col], Wsrc[col + 4], Wsrc[col + 8], Wsrc[col + 12] };
        ((float4*)g_w32)[j] = rnd4(v);
        return;
    }
    int k2 = j - 786432;
    if (k2 < 16384) {                // ---- Wo round: 64*1024 floats = 16384 float4
        ((float4*)g_wo32)[k2] = rnd4(((const float4*)Wo)[k2]);
        return;
    }
    int b = k2 - 16384;              // ---- biases (0..767 float4)
    if (b < 768) {
        const float4* src = (b < 256) ? ((const float4*)bq + b)
                           : (b < 512) ? ((const float4*)bk + (b - 256))
                                       : ((const float4*)bv + (b - 512));
        ((float4*)g_b32)[b] = *src;
    }
}

// ======================= Kernel A: QKV projection ===========================
#define KA_STG   3
#define KA_STGB  32768
#define KA_SMEM  (KA_STG * KA_STGB)
__global__ void __launch_bounds__(256, 2)
kA()
{
    extern __shared__ char smc[];
    const uint32_t sb = (uint32_t)__cvta_generic_to_shared(smc);
    const int tid = threadIdx.x, wid = tid >> 5, lane = tid & 31;
    const int g = lane >> 2, t = lane & 3;
    const int wr = wid >> 2, wc = wid & 3;     // 2x4 warp grid, warp tile 64x32
    const int nb = blockIdx.x;                 // 24 feature tiles
    const int mb = blockIdx.y;                 // 32 sequence tiles

    auto load_stage = [&](int s, int kt) {
        const float* srcA = g_x32 + (size_t)(mb * 32 + kt) * 4096;
        const float* srcB = g_w32 + (size_t)(nb * 32 + kt) * 4096;
        const uint32_t dA = sb + s * KA_STGB;
        const uint32_t dB = dA + 16384;
#pragma unroll
        for (int i = 0; i < 4; i++) cpa_u(dA + (tid + i * 256) * 16, srcA + (tid + i * 256) * 4);
#pragma unroll
        for (int i = 0; i < 4; i++) cpa_u(dB + (tid + i * 256) * 16, srcB + (tid + i * 256) * 4);
        CP_COMMIT();
    };

    float acc[4][4][4];
#pragma unroll
    for (int a = 0; a < 4; a++)
#pragma unroll
        for (int b = 0; b < 4; b++)
#pragma unroll
            for (int c = 0; c < 4; c++) acc[a][b][c] = 0.f;

    load_stage(0, 0);
    load_stage(1, 1);

    for (int kt = 0; kt < 32; kt++) {
        const int s = kt % KA_STG;
        if (kt + 2 < 32) { load_stage((kt + 2) % KA_STG, kt + 2); CP_WAIT(2); }
        else if (kt == 30) { CP_WAIT(1); }
        else               { CP_WAIT(0); }
        __syncthreads();

        const char* sA = smc + s * KA_STGB + (size_t)(wr * 512 + g * 4 + t) * 16;
        const char* sB = smc + s * KA_STGB + 16384 + (size_t)(wc * 256 + g * 4 + t) * 16;
#pragma unroll
        for (int kp = 0; kp < 2; kp++) {
            uint4 bv[4];
#pragma unroll
            for (int nt = 0; nt < 4; nt++)
                bv[nt] = *(const uint4*)(sB + (size_t)(nt * 64 + kp * 32) * 16);
#pragma unroll
            for (int ki = 0; ki < 2; ki++) {
                const int ks = kp * 2 + ki;
                uint4 av[4];
#pragma unroll
                for (int mt = 0; mt < 4; mt++)
                    av[mt] = *(const uint4*)(sA + (size_t)(mt * 128 + ks * 32) * 16);
#pragma unroll
                for (int nt = 0; nt < 4; nt++) {
                    uint32_t b0 = ki ? bv[nt].z : bv[nt].x;
                    uint32_t b1 = ki ? bv[nt].w : bv[nt].y;
#pragma unroll
                    for (int mt = 0; mt < 4; mt++)
                        mma_m16n8k8(acc[mt][nt], av[mt].x, av[mt].y, av[mt].z, av[mt].w, b0, b1);
                }
            }
        }
        __syncthreads();
    }

    const int r0 = nb * 128, m0 = mb * 128;
#pragma unroll
    for (int mt = 0; mt < 4; mt++) {
#pragma unroll
        for (int nt = 0; nt < 4; nt++) {
            int row = m0 + wr * 64 + mt * 16 + g;
            int col = r0 + wc * 32 + nt * 8 + 2 * t;
            float b0 = g_b32[col], b1 = g_b32[col + 1];
            float2 v0 = { rndf(acc[mt][nt][0] + b0), rndf(acc[mt][nt][1] + b1) };
            float2 v1 = { rndf(acc[mt][nt][2] + b0), rndf(acc[mt][nt][3] + b1) };
            *(float2*)&g_qkv[(size_t)row * QKV_LD + col] = v0;
            *(float2*)&g_qkv[(size_t)(row + 8) * QKV_LD + col] = v1;
        }
    }
}

// ======================= Kernel B: kp/vp (split-K=8, occ 2) =================
// A-operands passed as raw fp32 bits (HW tf32 truncation) — no in-loop cvt.
#define B_SMEM_BYTES ((2u * 256u * 36u + 2u * 32u * 72u) * 4u)
__global__ void __launch_bounds__(256, 2)
kB(const float* __restrict__ Ew, const float* __restrict__ Fw)
{
    extern __shared__ float sm[];
    float* As = sm;                   // [2][256][36]
    float* Bs = sm + 2 * 256 * 36;    // [2][32][72]
    const int tid = threadIdx.x;
    const int s = blockIdx.x;         // ksplit 0..7
    const int m = blockIdx.y;         // matrix 0..31
    const float* Aw = (m < 16) ? (Ew + (size_t)m * dK * dN)
                               : (Fw + (size_t)(m - 16) * dK * dN);
    const int cbase = (m < 16) ? (1024 + m * 64) : (2048 + (m - 16) * 64);
    const int kbase0 = s * 512;

    auto load_tile = [&](int buf, int kb) {
        float* dA = As + buf * 256 * 36;
        float* dB = Bs + buf * 32 * 72;
#pragma unroll
        for (int i = 0; i < 8; i++) {
            int e = tid + i * 256;
            int row = e >> 3, q = e & 7;
            cpa(dA + row * 36 + q * 4, Aw + (size_t)row * dN + kb + q * 4);
        }
#pragma unroll
        for (int i = 0; i < 2; i++) {
            int e = tid + i * 256;
            int row = e >> 4, q = e & 15;
            cpa(dB + row * 72 + q * 4, g_qkv + (size_t)(kb + row) * QKV_LD + cbase + q * 4);
        }
    };

    const int lane = tid & 31, w = tid >> 5;
    const int g = lane >> 2, t = lane & 3;
    const int wr = w >> 1, wc = w & 1;   // 4x2 warp grid, warp tile 64x32

    float acc[4][4][4];
#pragma unroll
    for (int a = 0; a < 4; a++)
#pragma unroll
        for (int b = 0; b < 4; b++)
#pragma unroll
            for (int c = 0; c < 4; c++) acc[a][b][c] = 0.f;

    load_tile(0, kbase0);
    CP_COMMIT();
    const int NKT = 512 / 32;
    for (int kt = 0; kt < NKT; kt++) {
        if (kt + 1 < NKT) { load_tile((kt + 1) & 1, kbase0 + (kt + 1) * 32); CP_COMMIT(); CP_WAIT(1); }
        else              { CP_WAIT(0); }
        __syncthreads();
        const float* A = As + (kt & 1) * 256 * 36;
        const float* B = Bs + (kt & 1) * 32 * 72;
#pragma unroll
        for (int ks = 0; ks < 4; ks++) {
            const int k = ks * 8;
            uint32_t af[4][4];
#pragma unroll
            for (int mt = 0; mt < 4; mt++) {
                const float* ap = A + (wr * 64 + mt * 16 + g) * 36 + k + t;
                af[mt][0] = __float_as_uint(ap[0]);           // raw bits -> HW tf32 trunc
                af[mt][1] = __float_as_uint(ap[8 * 36]);
                af[mt][2] = __float_as_uint(ap[4]);
                af[mt][3] = __float_as_uint(ap[8 * 36 + 4]);
            }
#pragma unroll
            for (int nt = 0; nt < 4; nt++) {
                const int col = wc * 32 + nt * 8 + g;
                uint32_t b0 = __float_as_uint(B[(k + t) * 72 + col]);       // pre-rounded
                uint32_t b1 = __float_as_uint(B[(k + t + 4) * 72 + col]);
#pragma unroll
                for (int mt = 0; mt < 4; mt++)
                    mma_m16n8k8(acc[mt][nt], af[mt][0], af[mt][1], af[mt][2], af[mt][3], b0, b1);
            }
        }
        __syncthreads();
    }

    float* base = g_part + (size_t)(s * 32 + m) * (dK * dE);
#pragma unroll
    for (int mt = 0; mt < 4; mt++) {
#pragma unroll
        for (int nt = 0; nt < 4; nt++) {
            int j = wr * 64 + mt * 16 + g;
            int e = wc * 32 + nt * 8 + 2 * t;
            float2 v0 = { acc[mt][nt][0], acc[mt][nt][1] };
            float2 v1 = { acc[mt][nt][2], acc[mt][nt][3] };
            *(float2*)&base[(size_t)j * dE + e] = v0;
            *(float2*)&base[(size_t)(j + 8) * dE + e] = v1;
        }
    }
}

// ======================= Kernel B2: split-K reduce + bias + round ===========
__global__ void __launch_bounds__(256, 1)
kB2(const float* __restrict__ Eb, const float* __restrict__ Fb)
{
    int idx = blockIdx.x * 256 + threadIdx.x;    // float4 index, 131072 total
    int m = idx >> 12;
    int r = idx & 4095;
    int j = r >> 4;
    float4 sum = make_float4(0.f, 0.f, 0.f, 0.f);
#pragma unroll
    for (int s = 0; s < NSPLIT; s++) {
        const float4* p = (const float4*)(g_part + (size_t)(s * 32 + m) * (dK * dE));
        float4 v = p[r];
        sum.x += v.x; sum.y += v.y; sum.z += v.z; sum.w += v.w;
    }
    float b = (m < 16) ? Eb[m * dK + j] : Fb[(m - 16) * dK + j];
    sum.x += b; sum.y += b; sum.z += b; sum.w += b;
    float4* outp = (m < 16) ? (float4*)(g_kp + (size_t)m * (dK * dE))
                            : (float4*)(g_vp + (size_t)(m - 16) * (dK * dE));
    outp[r] = rnd4(sum);
}

// ======================= Kernel B3: kp/vp -> fragment layouts ===============
__global__ void __launch_bounds__(256, 1)
kB3()
{
    int idx = blockIdx.x * 256 + threadIdx.x;    // 131072 threads
    if (idx < 65536) {
        int h = idx >> 12, s = idx & 4095;
        int nt = s >> 7, r = s & 127;
        int kb = r >> 5, r2 = r & 31, g = r2 >> 2, t = r2 & 3;
        int j = nt * 8 + g, c = kb * 16 + t;
        const float* src = g_kp + (size_t)h * 16384 + (size_t)j * 64 + c;
        float4 v = { src[0], src[4], src[8], src[12] };
        ((float4*)g_kp2)[idx] = v;
    } else {
        int i2 = idx - 65536;
        int h = i2 >> 12, s = i2 & 4095;
        int et = s >> 9, r = s & 511;
        int jb = r >> 5, r2 = r & 31, g = r2 >> 2, t = r2 & 3;
        int e = et * 8 + g, jb16 = jb * 16;
        const float* base = g_vp + (size_t)h * 16384;
        float4 v = { base[(size_t)(jb16 + 2 * t) * 64 + e],
                     base[(size_t)(jb16 + 2 * t + 1) * 64 + e],
                     base[(size_t)(jb16 + 8 + 2 * t) * 64 + e],
                     base[(size_t)(jb16 + 9 + 2 * t) * 64 + e] };
        ((float4*)g_vp2)[i2] = v;
    }
}

// ======================= Kernel C: multi-tile register attention ============
#define C3_QS     (128 * 68)              // one q buffer (floats)
#define C3_KP     (2 * C3_QS)             // 17408
#define C3_VP     (C3_KP + 16384)
#define C3_FLOATS (C3_VP + 16384)         // 50176 floats = 200704 B
#define C3_BYTES  (C3_FLOATS * 4u)
__global__ void __launch_bounds__(256, 1)
kC()
{
    extern __shared__ float sm[];
    float* qsA = sm;                 // [128][68] buffer 0
    float* qsB = sm + C3_QS;         // [128][68] buffer 1
    float* kp2 = sm + C3_KP;         // 16384 floats
    float* vp2 = sm + C3_VP;         // 16384 floats

    const int tid = threadIdx.x;
    const int h = blockIdx.y;
    const int base_tile = blockIdx.x * 4;

    auto load_q = [&](float* dst, int tile) {
        int n0 = (base_tile + tile) * 128;
#pragma unroll
        for (int i = 0; i < 8; i++) {
            int e = tid + i * 256;
            int row = e >> 4, q = e & 15;
            cpa(dst + row * 68 + q * 4, g_qkv + (size_t)(n0 + row) * QKV_LD + h * 64 + q * 4);
        }
        CP_COMMIT();
    };

    load_q(qsA, 0);                                  // group 0
#pragma unroll
    for (int i = 0; i < 16; i++) {
        int e = tid + i * 256;
        cpa(kp2 + e * 4, g_kp2 + (size_t)h * 16384 + e * 4);
    }
#pragma unroll
    for (int i = 0; i < 16; i++) {
        int e = tid + i * 256;
        cpa(vp2 + e * 4, g_vp2 + (size_t)h * 16384 + e * 4);
    }
    CP_COMMIT();                                     // group 1
    load_q(qsB, 1);                                  // group 2

    const int lane = tid & 31, w = tid >> 5;
    const int g = lane >> 2, t = lane & 3;

    for (int it = 0; it < 4; it++) {
        if (it == 3) { CP_WAIT(0); } else { CP_WAIT(1); }
        __syncthreads();
        float* qs = (it & 1) ? qsB : qsA;
        const int n0 = (base_tile + it) * 128;

        float att[32][4];
#pragma unroll
        for (int nt = 0; nt < 32; nt++)
#pragma unroll
            for (int c = 0; c < 4; c++) att[nt][c] = 0.f;

        const float* qbase = qs + (w * 16 + g) * 68;
#pragma unroll
        for (int kb = 0; kb < 4; kb++) {
            uint32_t a[2][4];
#pragma unroll
            for (int ks2 = 0; ks2 < 2; ks2++) {
                const float* ap = qbase + kb * 16 + ks2 * 8 + t;
                a[ks2][0] = __float_as_uint(ap[0]);
                a[ks2][1] = __float_as_uint(ap[8 * 68]);
                a[ks2][2] = __float_as_uint(ap[4]);
                a[ks2][3] = __float_as_uint(ap[8 * 68 + 4]);
            }
#pragma unroll
            for (int nt = 0; nt < 32; nt++) {
                uint4 bv = *(const uint4*)(kp2 + (size_t)(nt * 128 + kb * 32 + g * 4 + t) * 4);
                mma_m16n8k8(att[nt], a[0][0], a[0][1], a[0][2], a[0][3], bv.x, bv.y);
                mma_m16n8k8(att[nt], a[1][0], a[1][1], a[1][2], a[1][3], bv.z, bv.w);
            }
        }

        __syncthreads();
        if (it + 2 < 4) load_q(qs, it + 2);

        float mx0 = -1e30f, mx1 = -1e30f;
#pragma unroll
        for (int nt = 0; nt < 32; nt++) {
            att[nt][0] *= 0.125f; att[nt][1] *= 0.125f;
            att[nt][2] *= 0.125f; att[nt][3] *= 0.125f;
            mx0 = fmaxf(mx0, fmaxf(att[nt][0], att[nt][1]));
            mx1 = fmaxf(mx1, fmaxf(att[nt][2], att[nt][3]));
        }
        mx0 = fmaxf(mx0, __shfl_xor_sync(0xffffffffu, mx0, 1));
        mx0 = fmaxf(mx0, __shfl_xor_sync(0xffffffffu, mx0, 2));
        mx1 = fmaxf(mx1, __shfl_xor_sync(0xffffffffu, mx1, 1));
        mx1 = fmaxf(mx1, __shfl_xor_sync(0xffffffffu, mx1, 2));

        float s0 = 0.f, s1 = 0.f;
#pragma unroll
        for (int nt = 0; nt < 32; nt++) {
            float v0 = __expf(att[nt][0] - mx0);
            float v1 = __expf(att[nt][1] - mx0);
            float v2 = __expf(att[nt][2] - mx1);
            float v3 = __expf(att[nt][3] - mx1);
            att[nt][0] = v0; att[nt][1] = v1; att[nt][2] = v2; att[nt][3] = v3;
            s0 += v0 + v1; s1 += v2 + v3;
        }
        s0 += __shfl_xor_sync(0xffffffffu, s0, 1);
        s0 += __shfl_xor_sync(0xffffffffu, s0, 2);
        s1 += __shfl_xor_sync(0xffffffffu, s1, 1);
        s1 += __shfl_xor_sync(0xffffffffu, s1, 2);
        const float inv0 = 1.f / s0, inv1 = 1.f / s1;
#pragma unroll
        for (int nt = 0; nt < 32; nt++) {
            att[nt][0] = rndf(att[nt][0] * inv0);
            att[nt][1] = rndf(att[nt][1] * inv0);
            att[nt][2] = rndf(att[nt][2] * inv1);
            att[nt][3] = rndf(att[nt][3] * inv1);
        }

        float zacc[8][4];
#pragma unroll
        for (int et = 0; et < 8; et++)
#pragma unroll
            for (int c = 0; c < 4; c++) zacc[et][c] = 0.f;

#pragma unroll
        for (int jb = 0; jb < 16; jb++) {
            uint32_t aA0 = __float_as_uint(att[2 * jb][0]);
            uint32_t aA1 = __float_as_uint(att[2 * jb][2]);
            uint32_t aA2 = __float_as_uint(att[2 * jb][1]);
            uint32_t aA3 = __float_as_uint(att[2 * jb][3]);
            uint32_t aB0 = __float_as_uint(att[2 * jb + 1][0]);
            uint32_t aB1 = __float_as_uint(att[2 * jb + 1][2]);
            uint32_t aB2 = __float_as_uint(att[2 * jb + 1][1]);
            uint32_t aB3 = __float_as_uint(att[2 * jb + 1][3]);
#pragma unroll
            for (int et = 0; et < 8; et++) {
                uint4 bv = *(const uint4*)(vp2 + (size_t)(et * 512 + jb * 32 + g * 4 + t) * 4);
                mma_m16n8k8(zacc[et], aA0, aA1, aA2, aA3, bv.x, bv.y);
                mma_m16n8k8(zacc[et], aB0, aB1, aB2, aB3, bv.z, bv.w);
            }
        }

        const int row = n0 + w * 16 + g;
#pragma unroll
        for (int et = 0; et < 8; et++) {
            int col = h * 64 + et * 8 + 2 * t;
            float2 v0 = { rndf(zacc[et][0]), rndf(zacc[et][1]) };
            float2 v1 = { rndf(zacc[et][2]), rndf(zacc[et][3]) };
            *(float2*)&g_z[(size_t)row * (dH * dE) + col] = v0;
            *(float2*)&g_z[(size_t)(row + 8) * (dH * dE) + col] = v1;
        }
    }
}

// ======================= Kernel D: output projection ========================
#define D_SMEM_BYTES ((2u * 128u * 36u + 2u * 64u * 36u) * 4u)
__global__ void __launch_bounds__(256, 1)
kD(float* __restrict__ out)
{
    extern __shared__ float sm[];
    float* Zs = sm;                  // [2][128][36]
    float* Ws = sm + 2 * 128 * 36;   // [2][64][36]
    const int tid = threadIdx.x;
    const int n0 = blockIdx.x * 128;

    auto load_tile = [&](int buf, int kb) {
        float* dZ = Zs + buf * 128 * 36;
        float* dW = Ws + buf * 64 * 36;
#pragma unroll
        for (int i = 0; i < 4; i++) {
            int e = tid + i * 256;
            int row = e >> 3, q = e & 7;
            cpa(dZ + row * 36 + q * 4, g_z + (size_t)(n0 + row) * (dH * dE) + kb + q * 4);
        }
#pragma unroll
        for (int i = 0; i < 2; i++) {
            int e = tid + i * 256;
            int row = e >> 3, q = e & 7;
            cpa(dW + row * 36 + q * 4, g_wo32 + (size_t)row * (dH * dE) + kb + q * 4);
        }
    };

    const int lane = tid & 31, w = tid >> 5;
    const int g = lane >> 2, t = lane & 3;
    const int wr = w >> 2, wc = w & 3;   // 2x4 warp grid, warp tile 64x16

    float acc[4][2][4];
#pragma unroll
    for (int a = 0; a < 4; a++)
#pragma unroll
        for (int b = 0; b < 2; b++)
#pragma unroll
            for (int c = 0; c < 4; c++) acc[a][b][c] = 0.f;

    load_tile(0, 0);
    CP_COMMIT();
    const int NKT = (dH * dE) / 32;
    for (int kt = 0; kt < NKT; kt++) {
        if (kt + 1 < NKT) { load_tile((kt + 1) & 1, (kt + 1) * 32); CP_COMMIT(); CP_WAIT(1); }
        else              { CP_WAIT(0); }
        __syncthreads();
        const float* Z = Zs + (kt & 1) * 128 * 36;
        const float* W2 = Ws + (kt & 1) * 64 * 36;
#pragma unroll
        for (int ks = 0; ks < 4; ks++) {
            const int k = ks * 8;
            uint32_t af[4][4];
#pragma unroll
            for (int mt = 0; mt < 4; mt++) {
                const float* ap = Z + (wr * 64 + mt * 16 + g) * 36 + k + t;
                af[mt][0] = __float_as_uint(ap[0]);
                af[mt][1] = __float_as_uint(ap[8 * 36]);
                af[mt][2] = __float_as_uint(ap[4]);
                af[mt][3] = __float_as_uint(ap[8 * 36 + 4]);
            }
#pragma unroll
            for (int nt = 0; nt < 2; nt++) {
                const float* bp = W2 + (wc * 16 + nt * 8 + g) * 36 + k + t;
                uint32_t b0 = __float_as_uint(bp[0]);
                uint32_t b1 = __float_as_uint(bp[4]);
#pragma unroll
                for (int mt = 0; mt < 4; mt++)
                    mma_m16n8k8(acc[mt][nt], af[mt][0], af[mt][1], af[mt][2], af[mt][3], b0, b1);
            }
        }
        __syncthreads();
    }

#pragma unroll
    for (int mt = 0; mt < 4; mt++)
#pragma unroll
        for (int nt = 0; nt < 2; nt++) {
            int row = n0 + wr * 64 + mt * 16 + g;
            int col = wc * 16 + nt * 8 + 2 * t;
            float2 v0 = { acc[mt][nt][0], acc[mt][nt][1] };
            float2 v1 = { acc[mt][nt][2], acc[mt][nt][3] };
            *(float2*)&out[(size_t)row * dE + col] = v0;
            *(float2*)&out[(size_t)(row + 8) * dE + col] = v1;
        }
}

// ======================= launcher ===========================================
extern "C" void kernel_launch(void* const* d_in, const int* in_sizes, int n_in,
                              void* d_out, int out_size)
{
    const float* x  = (const float*)d_in[0];
    const float* Wq = (const float*)d_in[1];
    const float* bq = (const float*)d_in[2];
    const float* Wk = (const float*)d_in[3];
    const float* bk = (const float*)d_in[4];
    const float* Wv = (const float*)d_in[5];
    const float* bv = (const float*)d_in[6];
    const float* Ew = (const float*)d_in[7];
    const float* Eb = (const float*)d_in[8];
    const float* Fw = (const float*)d_in[9];
    const float* Fb = (const float*)d_in[10];
    const float* Wo = (const float*)d_in[11];
    float* out = (float*)d_out;

    cudaFuncSetAttribute(kA, cudaFuncAttributeMaxDynamicSharedMemorySize, KA_SMEM);
    cudaFuncSetAttribute(kB, cudaFuncAttributeMaxDynamicSharedMemorySize, B_SMEM_BYTES);
    cudaFuncSetAttribute(kC, cudaFuncAttributeMaxDynamicSharedMemorySize, C3_BYTES);
    cudaFuncSetAttribute(kD, cudaFuncAttributeMaxDynamicSharedMemorySize, D_SMEM_BYTES);

    kPre<<<7235, 256>>>(x, Wq, Wk, Wv, bq, bk, bv, Wo);
    kA<<<dim3(24, 32), 256, KA_SMEM>>>();
    kB<<<dim3(NSPLIT, 32), 256, B_SMEM_BYTES>>>(Ew, Fw);
    kB2<<<512, 256>>>(Eb, Fb);
    kB3<<<512, 256>>>();
    kC<<<dim3(8, 16), 256, C3_BYTES>>>();
    kD<<<32, 256, D_SMEM_BYTES>>>(out);
}